// round 11
// baseline (speedup 1.0000x reference)
#include <cuda_runtime.h>

#define NB 16
#define NH 16
#define NI 512
#define NE 512
#define IE (NI * NE)
#define JSPLIT 4
#define EMB_BLOCKS 256
#define GEMM_BLOCKS 128

// emb partials (device scratch; allocations forbidden)
__device__ float g_embp[JSPLIT][NB * NH * NE];  // 2 MB

// Producer->consumer gate: all counters MONOTONIC across graph replays
// (no resets -> no replay races). Launch L: emb arrivals push g_arrive by
// 256 and the 256th bumps g_ready L -> L+1; gemm entry tickets 128L..128L+127
// give target L+1.
__device__ unsigned g_arrive = 0;
__device__ unsigned g_ready  = 0;
__device__ unsigned g_entry  = 0;

// ---------------------------------------------------------------------------
// One kernel, grid 384: bids 0-255 = emb phase (R8 core), 256-383 = gemm
// phase (R8 core) behind the spin gate. Emb bids strictly precede gemm bids
// in dispatch order -> gate is deadlock-free at any occupancy.
// ---------------------------------------------------------------------------
__global__ __launch_bounds__(256, 2) void fused_kernel(const float* __restrict__ x,
                                                       const float* __restrict__ wv,
                                                       const float* __restrict__ w,
                                                       const float* __restrict__ bias,
                                                       float* __restrict__ out) {
    const int t = threadIdx.x;

    __shared__ union {
        float red[8][32][32];                            // 32 KB (emb)
        struct { float a[64][68]; float b[64][68]; } g;  // 34.8 KB (gemm)
    } sm;

    if (blockIdx.x < EMB_BLOCKS) {
        // ================= emb phase (R8 verbatim) =========================
        const int bid = blockIdx.x;

        // Bias init of the output (gemm accumulates on top).
        {
            const int oidx = bid * 256 + t;            // 0 .. 65535
            const float bv = bias[oidx & (NE - 1)];
            out[oidx]         = bv;
            out[oidx + 65536] = bv;
        }

        const int el  = t & 31;            // e lane (coalesced)
        const int sl  = t >> 5;            // j slice (warp id) 0..7
        const int ec  = bid & 15;          // e chunk 0..15
        const int hg  = (bid >> 4) & 1;    // h half
        const int bg  = (bid >> 5) & 1;    // b half
        const int js  = bid >> 6;          // j split 0..3

        const int e = ec * 32 + el;
        const float* xp = x  + bg * 8 * IE + e;
        const float* wp = wv + hg * 8 * IE + e;

        float acc[8][8];
#pragma unroll
        for (int i = 0; i < 8; ++i)
#pragma unroll
            for (int k = 0; k < 8; ++k) acc[i][k] = 0.f;

        const int j0 = js * 128;
#pragma unroll 2
        for (int jj = 0; jj < 16; ++jj) {
            const int joff = (j0 + sl + jj * 8) * NE;
            float xv[8], wv8[8];
#pragma unroll
            for (int i = 0; i < 8; ++i) xv[i]  = __ldg(xp + i * IE + joff);
#pragma unroll
            for (int k = 0; k < 8; ++k) wv8[k] = __ldg(wp + k * IE + joff);
#pragma unroll
            for (int i = 0; i < 8; ++i)
#pragma unroll
                for (int k = 0; k < 8; ++k)
                    acc[i][k] = fmaf(xv[i], wv8[k], acc[i][k]);
        }

        const int b0 = bg * 8, h0 = hg * 8;
#pragma unroll
        for (int half = 0; half < 2; ++half) {
            __syncthreads();
#pragma unroll
            for (int ik = 0; ik < 32; ++ik) {
                const int ikf = half * 32 + ik;
                sm.red[sl][ik][el] = acc[ikf >> 3][ikf & 7];
            }
            __syncthreads();
#pragma unroll
            for (int r = 0; r < 4; ++r) {
                const int ik = r * 8 + sl;
                float s = 0.f;
#pragma unroll
                for (int q = 0; q < 8; ++q) s += sm.red[q][ik][el];
                const int ikf = half * 32 + ik;
                const int b = b0 + (ikf >> 3);
                const int h = h0 + (ikf & 7);
                g_embp[js][(b * NH + h) * NE + e] = s;
            }
        }

        // ---- arrive: publish writes, then signal ----
        __threadfence();
        __syncthreads();
        if (t == 0) {
            const unsigned tk = atomicAdd(&g_arrive, 1u);
            if ((tk & (EMB_BLOCKS - 1)) == EMB_BLOCKS - 1) {
                __threadfence();
                atomicAdd(&g_ready, 1u);
            }
        }
    } else {
        // ================= gemm phase (R8 verbatim) ========================
        // ---- gate: wait for this launch's emb phase ----
        if (t == 0) {
            const unsigned tk = atomicAdd(&g_entry, 1u);
            const unsigned target = tk / GEMM_BLOCKS + 1u;
            while (*(volatile unsigned*)&g_ready < target) __nanosleep(64);
        }
        __syncthreads();
        __threadfence();

        const int bid = blockIdx.x - EMB_BLOCKS;  // 0..127 = 4 mt x 8 nt x 4 kt
        const int kt  = bid & 3;
        const int nt  = (bid >> 2) & 7;
        const int mt  = bid >> 5;
        const int m0 = mt * 64, n0 = nt * 64;

        const int tx = t & 15;   // n micro-tile
        const int ty = t >> 4;   // m micro-tile
        float acc[4][4];
#pragma unroll
        for (int i = 0; i < 4; ++i)
#pragma unroll
            for (int j = 0; j < 4; ++j) acc[i][j] = 0.f;

#pragma unroll
        for (int kc = 0; kc < 2; ++kc) {
            const int k0 = kt * 128 + kc * 64;
            if (kc) __syncthreads();   // previous chunk consumed before reload

#pragma unroll
            for (int r = 0; r < 4; ++r) {
                const int lin = t + r * 256;        // 0..1023 float4 slots
                const int row = lin >> 4;           // 0..63
                const int kq  = (lin & 15) * 4;     // 0..60
                const int aoff = (m0 + row) * NE + k0 + kq;
                float4 a = *(const float4*)&g_embp[0][aoff];
#pragma unroll
                for (int p = 1; p < JSPLIT; ++p) {
                    const float4 v = *(const float4*)&g_embp[p][aoff];
                    a.x += v.x; a.y += v.y; a.z += v.z; a.w += v.w;
                }
                sm.g.a[kq + 0][row] = a.x;
                sm.g.a[kq + 1][row] = a.y;
                sm.g.a[kq + 2][row] = a.z;
                sm.g.a[kq + 3][row] = a.w;
                const float4 b4 = *(const float4*)&w[(n0 + row) * NE + k0 + kq];
                sm.g.b[kq + 0][row] = b4.x;
                sm.g.b[kq + 1][row] = b4.y;
                sm.g.b[kq + 2][row] = b4.z;
                sm.g.b[kq + 3][row] = b4.w;
            }
            __syncthreads();

#pragma unroll 8
            for (int kk = 0; kk < 64; ++kk) {
                const float4 av = *(const float4*)&sm.g.a[kk][ty * 4];
                const float4 bv = *(const float4*)&sm.g.b[kk][tx * 4];
                const float a[4] = {av.x, av.y, av.z, av.w};
                const float b[4] = {bv.x, bv.y, bv.z, bv.w};
#pragma unroll
                for (int i = 0; i < 4; ++i)
#pragma unroll
                    for (int j = 0; j < 4; ++j)
                        acc[i][j] = fmaf(a[i], b[j], acc[i][j]);
            }
        }

        // Split-K accumulate directly into the bias-initialized output.
#pragma unroll
        for (int i = 0; i < 4; ++i) {
            float* op = &out[(m0 + ty * 4 + i) * NE + n0 + tx * 4];
#pragma unroll
            for (int j = 0; j < 4; ++j)
                atomicAdd(op + j, acc[i][j]);
        }
    }
}

extern "C" void kernel_launch(void* const* d_in, const int* in_sizes, int n_in,
                              void* d_out, int out_size) {
    const float* x    = (const float*)d_in[0];  // [16,1,512,512]
    // d_in[1] = W_q, d_in[2] = W_k: mathematically dead (softmax cols sum to 1)
    const float* wv   = (const float*)d_in[3];  // [1,16,512,512]
    const float* mlpw = (const float*)d_in[4];  // [512,512]
    const float* mlpb = (const float*)d_in[5];  // [512]
    float* out = (float*)d_out;                 // [16,16,512]

    fused_kernel<<<EMB_BLOCKS + GEMM_BLOCKS, 256>>>(x, wv, mlpw, mlpb, out);
}

// round 12
// speedup vs baseline: 1.2684x; 1.2684x over previous
#include <cuda_runtime.h>

#define NB 16
#define NH 16
#define NI 512
#define NE 512
#define IE (NI * NE)
#define JSPLIT 4

// emb partials (device scratch; allocations forbidden)
__device__ float g_embp[JSPLIT][NB * NH * NE];  // 2 MB

// ---------------------------------------------------------------------------
// Kernel 1 (R8 best, verbatim): emb partials + bias-init of out.
// g_embp[js][b,h,e] = sum_{j in 128-slice} x[b,j,e]*Wv[h,j,e]
// Block = 8b x 8h x 32e x 128j; 256 threads = 32 e-lanes x 8 j-slices;
// per j: 16 broadcast LDG.32 + 64 FMA into an 8x8 register tile.
// Grid 256 -> one wave at 2 blocks/SM.
// ---------------------------------------------------------------------------
__global__ __launch_bounds__(256) void emb_kernel(const float* __restrict__ x,
                                                  const float* __restrict__ wv,
                                                  const float* __restrict__ bias,
                                                  float* __restrict__ out) {
    const int t   = threadIdx.x;
    const int bid = blockIdx.x;        // 256 blocks

    // Bias init of the output (gemm accumulates on top).
    {
        const int oidx = bid * 256 + t;            // 0 .. 65535
        const float bv = bias[oidx & (NE - 1)];
        out[oidx]         = bv;
        out[oidx + 65536] = bv;
    }

    const int el  = t & 31;            // e lane (coalesced)
    const int sl  = t >> 5;            // j slice (warp id) 0..7
    const int ec  = bid & 15;          // e chunk 0..15
    const int hg  = (bid >> 4) & 1;    // h half
    const int bg  = (bid >> 5) & 1;    // b half
    const int js  = bid >> 6;          // j split 0..3

    const int e = ec * 32 + el;
    const float* xp = x  + bg * 8 * IE + e;
    const float* wp = wv + hg * 8 * IE + e;

    float acc[8][8];
#pragma unroll
    for (int i = 0; i < 8; ++i)
#pragma unroll
        for (int k = 0; k < 8; ++k) acc[i][k] = 0.f;

    const int j0 = js * 128;
#pragma unroll 2
    for (int jj = 0; jj < 16; ++jj) {
        const int joff = (j0 + sl + jj * 8) * NE;
        float xv[8], wv8[8];
#pragma unroll
        for (int i = 0; i < 8; ++i) xv[i]  = __ldg(xp + i * IE + joff);
#pragma unroll
        for (int k = 0; k < 8; ++k) wv8[k] = __ldg(wp + k * IE + joff);
#pragma unroll
        for (int i = 0; i < 8; ++i)
#pragma unroll
            for (int k = 0; k < 8; ++k)
                acc[i][k] = fmaf(xv[i], wv8[k], acc[i][k]);
    }

    __shared__ float red[8][32][32];   // [slice][ik][el] - conflict-free both ways
    const int b0 = bg * 8, h0 = hg * 8;
#pragma unroll
    for (int half = 0; half < 2; ++half) {
        __syncthreads();
#pragma unroll
        for (int ik = 0; ik < 32; ++ik) {
            const int ikf = half * 32 + ik;
            red[sl][ik][el] = acc[ikf >> 3][ikf & 7];
        }
        __syncthreads();
#pragma unroll
        for (int r = 0; r < 4; ++r) {
            const int ik = r * 8 + sl;
            float s = 0.f;
#pragma unroll
            for (int q = 0; q < 8; ++q) s += red[q][ik][el];
            const int ikf = half * 32 + ik;
            const int b = b0 + (ikf >> 3);
            const int h = h0 + (ikf & 7);
            g_embp[js][(b * NH + h) * NE + e] = s;
        }
    }
}

// ---------------------------------------------------------------------------
// Kernel 2 (PDL): out[m][n] += sum_k emb[m][k]*w[n][k]  (bias already in out)
// Launched with programmatic stream serialization: blocks start while emb
// drains, stage the B tile (independent of emb), then
// cudaGridDependencySynchronize() gates the A-read on emb grid completion.
// M=256,N=512,K=512. Tiles 64x64, split-K=8 (one 64-k stage) -> grid 256.
// A-load folds the 4 j-split partials. REDG atomicAdd epilogue.
// ---------------------------------------------------------------------------
__global__ __launch_bounds__(256) void gemm_kernel(const float* __restrict__ w,
                                                   float* __restrict__ out) {
    const int t   = threadIdx.x;
    const int bid = blockIdx.x;        // 256 = 4 mt x 8 nt x 8 kt
    const int kt  = bid & 7;
    const int nt  = (bid >> 3) & 7;
    const int mt  = bid >> 6;
    const int m0 = mt * 64, n0 = nt * 64, k0 = kt * 64;

    __shared__ __align__(16) float sa[64][68];  // [k][m]
    __shared__ __align__(16) float sb[64][68];  // [k][n]

    // ---- B tile first: independent of the emb kernel (overlaps its tail) --
#pragma unroll
    for (int r = 0; r < 4; ++r) {
        const int lin = t + r * 256;        // 1024 float4 slots
        const int row = lin >> 4;           // n 0..63
        const int kq  = (lin & 15) * 4;
        const float4 b4 = *(const float4*)&w[(n0 + row) * NE + k0 + kq];
        sb[kq + 0][row] = b4.x;
        sb[kq + 1][row] = b4.y;
        sb[kq + 2][row] = b4.z;
        sb[kq + 3][row] = b4.w;
    }

    // ---- gate: wait for the emb grid (all g_embp / out writes visible) ----
    cudaGridDependencySynchronize();

    // ---- A tile: 64m x 64k, folded over the 4 j-split partials ------------
#pragma unroll
    for (int r = 0; r < 4; ++r) {
        const int lin = t + r * 256;
        const int row = lin >> 4;           // m 0..63
        const int kq  = (lin & 15) * 4;
        const int aoff = (m0 + row) * NE + k0 + kq;
        float4 a = *(const float4*)&g_embp[0][aoff];
#pragma unroll
        for (int p = 1; p < JSPLIT; ++p) {
            const float4 v = *(const float4*)&g_embp[p][aoff];
            a.x += v.x; a.y += v.y; a.z += v.z; a.w += v.w;
        }
        sa[kq + 0][row] = a.x;
        sa[kq + 1][row] = a.y;
        sa[kq + 2][row] = a.z;
        sa[kq + 3][row] = a.w;
    }
    __syncthreads();

    const int tx = t & 15;   // n micro-tile
    const int ty = t >> 4;   // m micro-tile
    float acc[4][4];
#pragma unroll
    for (int i = 0; i < 4; ++i)
#pragma unroll
        for (int j = 0; j < 4; ++j) acc[i][j] = 0.f;

#pragma unroll 8
    for (int kk = 0; kk < 64; ++kk) {
        const float4 av = *(const float4*)&sa[kk][ty * 4];
        const float4 bv = *(const float4*)&sb[kk][tx * 4];
        const float a[4] = {av.x, av.y, av.z, av.w};
        const float b[4] = {bv.x, bv.y, bv.z, bv.w};
#pragma unroll
        for (int i = 0; i < 4; ++i)
#pragma unroll
            for (int j = 0; j < 4; ++j)
                acc[i][j] = fmaf(a[i], b[j], acc[i][j]);
    }

    // Split-K accumulate directly into the bias-initialized output.
#pragma unroll
    for (int i = 0; i < 4; ++i) {
        float* op = &out[(m0 + ty * 4 + i) * NE + n0 + tx * 4];
#pragma unroll
        for (int j = 0; j < 4; ++j)
            atomicAdd(op + j, acc[i][j]);
    }
}

extern "C" void kernel_launch(void* const* d_in, const int* in_sizes, int n_in,
                              void* d_out, int out_size) {
    const float* x    = (const float*)d_in[0];  // [16,1,512,512]
    // d_in[1] = W_q, d_in[2] = W_k: mathematically dead (softmax cols sum to 1)
    const float* wv   = (const float*)d_in[3];  // [1,16,512,512]
    const float* mlpw = (const float*)d_in[4];  // [512,512]
    const float* mlpb = (const float*)d_in[5];  // [512]
    float* out = (float*)d_out;                 // [16,16,512]

    emb_kernel<<<256, 256>>>(x, wv, mlpb, out);

    // gemm with programmatic dependent launch: overlaps its B staging with
    // emb's drain; the A-read is gated by cudaGridDependencySynchronize().
    cudaLaunchConfig_t cfg = {};
    cfg.gridDim  = dim3(256, 1, 1);
    cfg.blockDim = dim3(256, 1, 1);
    cfg.dynamicSmemBytes = 0;
    cudaLaunchAttribute attrs[1];
    attrs[0].id = cudaLaunchAttributeProgrammaticStreamSerialization;
    attrs[0].val.programmaticStreamSerializationAllowed = 1;
    cfg.attrs = attrs;
    cfg.numAttrs = 1;
    cudaLaunchKernelEx(&cfg, gemm_kernel, mlpw, (float*)d_out);
}

// round 13
// speedup vs baseline: 1.3735x; 1.0828x over previous
#include <cuda_runtime.h>

#define NB 16
#define NH 16
#define NI 512
#define NE 512
#define IE (NI * NE)
#define JSPLIT 4

// emb partials (device scratch; allocations forbidden)
__device__ float g_embp[JSPLIT][NB * NH * NE];  // 2 MB

// ---- tf32 helpers ----------------------------------------------------------
__device__ __forceinline__ unsigned f2tf32(float f) {
    unsigned u;
    asm("cvt.rna.tf32.f32 %0, %1;" : "=r"(u) : "f"(f));
    return u;
}
// split f into (hi, lo) both tf32-representable, hi+lo ~ f to ~2^-22
__device__ __forceinline__ void tf32_split(float f, unsigned& hi, unsigned& lo) {
    hi = f2tf32(f);
    lo = f2tf32(f - __uint_as_float(hi));
}
__device__ __forceinline__ void mma_tf32(float c[4], const unsigned a[4], const unsigned b[2]) {
    asm("mma.sync.aligned.m16n8k8.row.col.f32.tf32.tf32.f32 "
        "{%0,%1,%2,%3}, {%4,%5,%6,%7}, {%8,%9}, {%0,%1,%2,%3};"
        : "+f"(c[0]), "+f"(c[1]), "+f"(c[2]), "+f"(c[3])
        : "r"(a[0]), "r"(a[1]), "r"(a[2]), "r"(a[3]), "r"(b[0]), "r"(b[1]));
}

// ---------------------------------------------------------------------------
// Kernel 1 (R8 best, verbatim): emb partials + bias-init of out.
// g_embp[js][b,h,e] = sum_{j in 128-slice} x[b,j,e]*Wv[h,j,e]
// ---------------------------------------------------------------------------
__global__ __launch_bounds__(256) void emb_kernel(const float* __restrict__ x,
                                                  const float* __restrict__ wv,
                                                  const float* __restrict__ bias,
                                                  float* __restrict__ out) {
    const int t   = threadIdx.x;
    const int bid = blockIdx.x;        // 256 blocks

    // Bias init of the output (gemm accumulates on top).
    {
        const int oidx = bid * 256 + t;            // 0 .. 65535
        const float bv = bias[oidx & (NE - 1)];
        out[oidx]         = bv;
        out[oidx + 65536] = bv;
    }

    const int el  = t & 31;            // e lane (coalesced)
    const int sl  = t >> 5;            // j slice (warp id) 0..7
    const int ec  = bid & 15;          // e chunk 0..15
    const int hg  = (bid >> 4) & 1;    // h half
    const int bg  = (bid >> 5) & 1;    // b half
    const int js  = bid >> 6;          // j split 0..3

    const int e = ec * 32 + el;
    const float* xp = x  + bg * 8 * IE + e;
    const float* wp = wv + hg * 8 * IE + e;

    float acc[8][8];
#pragma unroll
    for (int i = 0; i < 8; ++i)
#pragma unroll
        for (int k = 0; k < 8; ++k) acc[i][k] = 0.f;

    const int j0 = js * 128;
#pragma unroll 2
    for (int jj = 0; jj < 16; ++jj) {
        const int joff = (j0 + sl + jj * 8) * NE;
        float xv[8], wv8[8];
#pragma unroll
        for (int i = 0; i < 8; ++i) xv[i]  = __ldg(xp + i * IE + joff);
#pragma unroll
        for (int k = 0; k < 8; ++k) wv8[k] = __ldg(wp + k * IE + joff);
#pragma unroll
        for (int i = 0; i < 8; ++i)
#pragma unroll
            for (int k = 0; k < 8; ++k)
                acc[i][k] = fmaf(xv[i], wv8[k], acc[i][k]);
    }

    __shared__ float red[8][32][32];   // [slice][ik][el] - conflict-free both ways
    const int b0 = bg * 8, h0 = hg * 8;
#pragma unroll
    for (int half = 0; half < 2; ++half) {
        __syncthreads();
#pragma unroll
        for (int ik = 0; ik < 32; ++ik) {
            const int ikf = half * 32 + ik;
            red[sl][ik][el] = acc[ikf >> 3][ikf & 7];
        }
        __syncthreads();
#pragma unroll
        for (int r = 0; r < 4; ++r) {
            const int ik = r * 8 + sl;
            float s = 0.f;
#pragma unroll
            for (int q = 0; q < 8; ++q) s += red[q][ik][el];
            const int ikf = half * 32 + ik;
            const int b = b0 + (ikf >> 3);
            const int h = h0 + (ikf & 7);
            g_embp[js][(b * NH + h) * NE + e] = s;
        }
    }
}

// ---------------------------------------------------------------------------
// Kernel 2 (PDL + tf32 tensor cores): out[m][n] += sum_k emb[m][k]*w[n][k]
// M=256,N=512,K=512. Tiles 64m x 64n, split-K=8 -> grid 256.
// B staged pre-gate (independent of emb), A-fold post-gate.
// Inner product: mma.sync.m16n8k8 tf32 with Markidis split
// (hi*hi + hi*lo + lo*hi -> rel err ~2^-22). 8 warps: warp w covers
// (w&3)*16 m-rows x (w>>2)*32 n-cols (4 n-tiles of 8).
// ---------------------------------------------------------------------------
__global__ __launch_bounds__(256) void gemm_kernel(const float* __restrict__ w,
                                                   float* __restrict__ out) {
    const int t   = threadIdx.x;
    const int bid = blockIdx.x;        // 256 = 4 mt x 8 nt x 8 kt
    const int kt  = bid & 7;
    const int nt  = (bid >> 3) & 7;
    const int mt  = bid >> 6;
    const int m0 = mt * 64, n0 = nt * 64, k0 = kt * 64;

    __shared__ __align__(16) float sa[64][68];  // [k][m]
    __shared__ __align__(16) float sb[64][68];  // [k][n]

    // ---- B tile first: independent of emb (overlaps its tail via PDL) -----
#pragma unroll
    for (int r = 0; r < 4; ++r) {
        const int lin = t + r * 256;        // 1024 float4 slots
        const int row = lin >> 4;           // n 0..63
        const int kq  = (lin & 15) * 4;
        const float4 b4 = *(const float4*)&w[(n0 + row) * NE + k0 + kq];
        sb[kq + 0][row] = b4.x;
        sb[kq + 1][row] = b4.y;
        sb[kq + 2][row] = b4.z;
        sb[kq + 3][row] = b4.w;
    }

    cudaGridDependencySynchronize();

    // ---- A tile: 64m x 64k, folded over the 4 j-split partials ------------
#pragma unroll
    for (int r = 0; r < 4; ++r) {
        const int lin = t + r * 256;
        const int row = lin >> 4;           // m 0..63
        const int kq  = (lin & 15) * 4;
        const int aoff = (m0 + row) * NE + k0 + kq;
        float4 a = *(const float4*)&g_embp[0][aoff];
#pragma unroll
        for (int p = 1; p < JSPLIT; ++p) {
            const float4 v = *(const float4*)&g_embp[p][aoff];
            a.x += v.x; a.y += v.y; a.z += v.z; a.w += v.w;
        }
        sa[kq + 0][row] = a.x;
        sa[kq + 1][row] = a.y;
        sa[kq + 2][row] = a.z;
        sa[kq + 3][row] = a.w;
    }
    __syncthreads();

    const int wid  = t >> 5;
    const int lane = t & 31;
    const int gid  = lane >> 2;        // group id 0..7
    const int tig  = lane & 3;         // thread in group 0..3
    const int mw = (wid & 3) * 16;     // warp m-offset in tile
    const int nw = (wid >> 2) * 32;    // warp n-offset in tile

    float c[4][4];                     // [ntile][creg]
#pragma unroll
    for (int i = 0; i < 4; ++i)
#pragma unroll
        for (int j = 0; j < 4; ++j) c[i][j] = 0.f;

#pragma unroll
    for (int ks = 0; ks < 8; ++ks) {   // 8 mma k-steps of 8
        const int kb = ks * 8;
        // A fragment (16x8, row-major): a0:(gid,tig) a1:(gid+8,tig) a2:(gid,tig+4) a3:(gid+8,tig+4)
        unsigned ah[4], al[4];
        tf32_split(sa[kb + tig    ][mw + gid    ], ah[0], al[0]);
        tf32_split(sa[kb + tig    ][mw + gid + 8], ah[1], al[1]);
        tf32_split(sa[kb + tig + 4][mw + gid    ], ah[2], al[2]);
        tf32_split(sa[kb + tig + 4][mw + gid + 8], ah[3], al[3]);
#pragma unroll
        for (int ntile = 0; ntile < 4; ++ntile) {
            // B fragment (8k x 8n, "col"): b0:(k=tig, n=gid) b1:(k=tig+4, n=gid)
            unsigned bh[2], bl[2];
            tf32_split(sb[kb + tig    ][nw + ntile * 8 + gid], bh[0], bl[0]);
            tf32_split(sb[kb + tig + 4][nw + ntile * 8 + gid], bh[1], bl[1]);
            mma_tf32(c[ntile], ah, bh);   // hi*hi
            mma_tf32(c[ntile], al, bh);   // lo*hi
            mma_tf32(c[ntile], ah, bl);   // hi*lo
        }
    }

    // Epilogue: c0:(gid, 2tig) c1:(gid, 2tig+1) c2:(gid+8, 2tig) c3:(gid+8, 2tig+1)
    const int gm = m0 + mw + gid;
    const int gn = n0 + nw + tig * 2;
#pragma unroll
    for (int ntile = 0; ntile < 4; ++ntile) {
        float* op = &out[gm * NE + gn + ntile * 8];
        atomicAdd(op + 0,          c[ntile][0]);
        atomicAdd(op + 1,          c[ntile][1]);
        atomicAdd(op + 8 * NE + 0, c[ntile][2]);
        atomicAdd(op + 8 * NE + 1, c[ntile][3]);
    }
}

extern "C" void kernel_launch(void* const* d_in, const int* in_sizes, int n_in,
                              void* d_out, int out_size) {
    const float* x    = (const float*)d_in[0];  // [16,1,512,512]
    // d_in[1] = W_q, d_in[2] = W_k: mathematically dead (softmax cols sum to 1)
    const float* wv   = (const float*)d_in[3];  // [1,16,512,512]
    const float* mlpw = (const float*)d_in[4];  // [512,512]
    const float* mlpb = (const float*)d_in[5];  // [512]
    float* out = (float*)d_out;                 // [16,16,512]

    emb_kernel<<<256, 256>>>(x, wv, mlpb, out);

    cudaLaunchConfig_t cfg = {};
    cfg.gridDim  = dim3(256, 1, 1);
    cfg.blockDim = dim3(256, 1, 1);
    cfg.dynamicSmemBytes = 0;
    cudaLaunchAttribute attrs[1];
    attrs[0].id = cudaLaunchAttributeProgrammaticStreamSerialization;
    attrs[0].val.programmaticStreamSerializationAllowed = 1;
    cfg.attrs = attrs;
    cfg.numAttrs = 1;
    cudaLaunchKernelEx(&cfg, gemm_kernel, mlpw, (float*)d_out);
}

// round 14
// speedup vs baseline: 1.5405x; 1.1216x over previous
#include <cuda_runtime.h>

#define NB 16
#define NH 16
#define NI 512
#define NE 512
#define IE (NI * NE)
#define JSPLIT 4

// emb partials (device scratch; allocations forbidden)
__device__ float g_embp[JSPLIT][NB * NH * NE];  // 2 MB

// ---- packed fp32x2 helpers -------------------------------------------------
__device__ __forceinline__ void fma2(unsigned long long& d,
                                     unsigned long long a, unsigned long long b) {
    asm("fma.rn.f32x2 %0, %1, %2, %0;" : "+l"(d) : "l"(a), "l"(b));
}

// ---- tf32 helpers ----------------------------------------------------------
__device__ __forceinline__ unsigned f2tf32(float f) {
    unsigned u;
    asm("cvt.rna.tf32.f32 %0, %1;" : "=r"(u) : "f"(f));
    return u;
}
__device__ __forceinline__ void tf32_split(float f, unsigned& hi, unsigned& lo) {
    hi = f2tf32(f);
    lo = f2tf32(f - __uint_as_float(hi));
}
__device__ __forceinline__ void mma_tf32(float c[4], const unsigned a[4], const unsigned b[2]) {
    asm("mma.sync.aligned.m16n8k8.row.col.f32.tf32.tf32.f32 "
        "{%0,%1,%2,%3}, {%4,%5,%6,%7}, {%8,%9}, {%0,%1,%2,%3};"
        : "+f"(c[0]), "+f"(c[1]), "+f"(c[2]), "+f"(c[3])
        : "r"(a[0]), "r"(a[1]), "r"(a[2]), "r"(a[3]), "r"(b[0]), "r"(b[1]));
}

// ---------------------------------------------------------------------------
// Kernel 1: emb partials + bias-init of out.
// g_embp[js][b,h,e] = sum_{j in 128-slice} x[b,j,e]*Wv[h,j,e]
// Thread tile 8b x 8h x 2e: float2 operands (12 LDG.64/j vs 16 LDG.32) and
// fma.rn.f32x2 accumulators (32 packed FMA/j vs 64 FFMA) -- both measured
// issue floors cut. Block = 8b x 8h x 32e x 128j; 256 thr = 16 e-pairs x
// 2 bq x 8 j-slices. Grid 256 = 16ec x 2hg x 2bg x 4js, 2 blocks/SM.
// ---------------------------------------------------------------------------
__global__ __launch_bounds__(256, 2) void emb_kernel(const float* __restrict__ x,
                                                     const float* __restrict__ wv,
                                                     const float* __restrict__ bias,
                                                     float* __restrict__ out) {
    const int t   = threadIdx.x;
    const int bid = blockIdx.x;        // 256 blocks

    // Bias init of the output (gemm accumulates on top).
    {
        const int oidx = bid * 256 + t;            // 0 .. 65535
        const float bv = bias[oidx & (NE - 1)];
        out[oidx]         = bv;
        out[oidx + 65536] = bv;
    }

    const int el  = t & 15;            // e pair lane
    const int bq  = (t >> 4) & 1;      // b quad select
    const int sl  = t >> 5;            // j slice (warp id) 0..7
    const int ec  = bid & 15;          // e chunk 0..15
    const int hg  = (bid >> 4) & 1;    // h half
    const int bg  = (bid >> 5) & 1;    // b half
    const int js  = bid >> 6;          // j split 0..3

    const int e0 = ec * 32 + el * 2;   // 8-byte aligned
    const float* xp = x  + (bg * 8 + bq * 4) * IE + e0;
    const float* wp = wv + hg * 8 * IE + e0;

    unsigned long long acc[4][8];      // packed float2 accumulators
#pragma unroll
    for (int i = 0; i < 4; ++i)
#pragma unroll
        for (int k = 0; k < 8; ++k) acc[i][k] = 0ull;

    const int j0 = js * 128;
#pragma unroll 2
    for (int jj = 0; jj < 16; ++jj) {
        const int joff = (j0 + sl + jj * 8) * NE;
        unsigned long long xv[4], wv8[8];
#pragma unroll
        for (int i = 0; i < 4; ++i)
            xv[i]  = *(const unsigned long long*)(xp + i * IE + joff);
#pragma unroll
        for (int k = 0; k < 8; ++k)
            wv8[k] = *(const unsigned long long*)(wp + k * IE + joff);
#pragma unroll
        for (int i = 0; i < 4; ++i)
#pragma unroll
            for (int k = 0; k < 8; ++k)
                fma2(acc[i][k], xv[i], wv8[k]);
    }

    // Reduce the 8 j-slices: two 16-ik halves through 32KB of float2 smem.
    __shared__ unsigned long long red[8][16][32];  // [slice][ik][lane]
    const int lane = t & 31;           // el | bq<<4
#pragma unroll
    for (int half = 0; half < 2; ++half) {
        __syncthreads();
#pragma unroll
        for (int ik = 0; ik < 16; ++ik) {
            const int ikf = half * 16 + ik;        // i*8 + k
            red[sl][ik][lane] = acc[ikf >> 3][ikf & 7];
        }
        __syncthreads();
#pragma unroll
        for (int r = 0; r < 2; ++r) {
            const int item = t + r * 256;          // 0..511
            const int ik   = item >> 5;            // 0..15
            const int ln   = item & 31;
            float2 s = make_float2(0.f, 0.f);
#pragma unroll
            for (int q = 0; q < 8; ++q) {
                const float2 v = *(const float2*)&red[q][ik][ln];
                s.x += v.x; s.y += v.y;
            }
            const int ikf = half * 16 + ik;
            const int b = bg * 8 + ((ln >> 4) & 1) * 4 + (ikf >> 3);
            const int h = hg * 8 + (ikf & 7);
            const int e = ec * 32 + (ln & 15) * 2;
            *(float2*)&g_embp[js][(b * NH + h) * NE + e] = s;
        }
    }
}

// ---------------------------------------------------------------------------
// Kernel 2 (R13 winner, verbatim): PDL + tf32 tensor cores.
// out[m][n] += sum_k emb[m][k]*w[n][k]  (bias already in out)
// ---------------------------------------------------------------------------
__global__ __launch_bounds__(256) void gemm_kernel(const float* __restrict__ w,
                                                   float* __restrict__ out) {
    const int t   = threadIdx.x;
    const int bid = blockIdx.x;        // 256 = 4 mt x 8 nt x 8 kt
    const int kt  = bid & 7;
    const int nt  = (bid >> 3) & 7;
    const int mt  = bid >> 6;
    const int m0 = mt * 64, n0 = nt * 64, k0 = kt * 64;

    __shared__ __align__(16) float sa[64][68];  // [k][m]
    __shared__ __align__(16) float sb[64][68];  // [k][n]

    // ---- B tile first: independent of emb (overlaps its tail via PDL) -----
#pragma unroll
    for (int r = 0; r < 4; ++r) {
        const int lin = t + r * 256;        // 1024 float4 slots
        const int row = lin >> 4;           // n 0..63
        const int kq  = (lin & 15) * 4;
        const float4 b4 = *(const float4*)&w[(n0 + row) * NE + k0 + kq];
        sb[kq + 0][row] = b4.x;
        sb[kq + 1][row] = b4.y;
        sb[kq + 2][row] = b4.z;
        sb[kq + 3][row] = b4.w;
    }

    cudaGridDependencySynchronize();

    // ---- A tile: 64m x 64k, folded over the 4 j-split partials ------------
#pragma unroll
    for (int r = 0; r < 4; ++r) {
        const int lin = t + r * 256;
        const int row = lin >> 4;           // m 0..63
        const int kq  = (lin & 15) * 4;
        const int aoff = (m0 + row) * NE + k0 + kq;
        float4 a = *(const float4*)&g_embp[0][aoff];
#pragma unroll
        for (int p = 1; p < JSPLIT; ++p) {
            const float4 v = *(const float4*)&g_embp[p][aoff];
            a.x += v.x; a.y += v.y; a.z += v.z; a.w += v.w;
        }
        sa[kq + 0][row] = a.x;
        sa[kq + 1][row] = a.y;
        sa[kq + 2][row] = a.z;
        sa[kq + 3][row] = a.w;
    }
    __syncthreads();

    const int wid  = t >> 5;
    const int lane = t & 31;
    const int gid  = lane >> 2;        // group id 0..7
    const int tig  = lane & 3;         // thread in group 0..3
    const int mw = (wid & 3) * 16;     // warp m-offset in tile
    const int nw = (wid >> 2) * 32;    // warp n-offset in tile

    float c[4][4];                     // [ntile][creg]
#pragma unroll
    for (int i = 0; i < 4; ++i)
#pragma unroll
        for (int j = 0; j < 4; ++j) c[i][j] = 0.f;

#pragma unroll
    for (int ks = 0; ks < 8; ++ks) {   // 8 mma k-steps of 8
        const int kb = ks * 8;
        unsigned ah[4], al[4];
        tf32_split(sa[kb + tig    ][mw + gid    ], ah[0], al[0]);
        tf32_split(sa[kb + tig    ][mw + gid + 8], ah[1], al[1]);
        tf32_split(sa[kb + tig + 4][mw + gid    ], ah[2], al[2]);
        tf32_split(sa[kb + tig + 4][mw + gid + 8], ah[3], al[3]);
#pragma unroll
        for (int ntile = 0; ntile < 4; ++ntile) {
            unsigned bh[2], bl[2];
            tf32_split(sb[kb + tig    ][nw + ntile * 8 + gid], bh[0], bl[0]);
            tf32_split(sb[kb + tig + 4][nw + ntile * 8 + gid], bh[1], bl[1]);
            mma_tf32(c[ntile], ah, bh);   // hi*hi
            mma_tf32(c[ntile], al, bh);   // lo*hi
            mma_tf32(c[ntile], ah, bl);   // hi*lo
        }
    }

    const int gm = m0 + mw + gid;
    const int gn = n0 + nw + tig * 2;
#pragma unroll
    for (int ntile = 0; ntile < 4; ++ntile) {
        float* op = &out[gm * NE + gn + ntile * 8];
        atomicAdd(op + 0,          c[ntile][0]);
        atomicAdd(op + 1,          c[ntile][1]);
        atomicAdd(op + 8 * NE + 0, c[ntile][2]);
        atomicAdd(op + 8 * NE + 1, c[ntile][3]);
    }
}

extern "C" void kernel_launch(void* const* d_in, const int* in_sizes, int n_in,
                              void* d_out, int out_size) {
    const float* x    = (const float*)d_in[0];  // [16,1,512,512]
    // d_in[1] = W_q, d_in[2] = W_k: mathematically dead (softmax cols sum to 1)
    const float* wv   = (const float*)d_in[3];  // [1,16,512,512]
    const float* mlpw = (const float*)d_in[4];  // [512,512]
    const float* mlpb = (const float*)d_in[5];  // [512]
    float* out = (float*)d_out;                 // [16,16,512]

    emb_kernel<<<256, 256>>>(x, wv, mlpb, out);

    cudaLaunchConfig_t cfg = {};
    cfg.gridDim  = dim3(256, 1, 1);
    cfg.blockDim = dim3(256, 1, 1);
    cfg.dynamicSmemBytes = 0;
    cudaLaunchAttribute attrs[1];
    attrs[0].id = cudaLaunchAttributeProgrammaticStreamSerialization;
    attrs[0].val.programmaticStreamSerializationAllowed = 1;
    cfg.attrs = attrs;
    cfg.numAttrs = 1;
    cudaLaunchKernelEx(&cfg, gemm_kernel, mlpw, (float*)d_out);
}